// round 6
// baseline (speedup 1.0000x reference)
#include <cuda_runtime.h>

// RMAC: x (64, 2048, 16, 16) f32 -> out (64, 14*2048) f32, L2-normalized rows.
// Regions (14): l1 1x [0,16)^2 /256 ; l2 4x 10x10 at offsets {0,4} /100 ;
// l3 9x 8x8 at offsets {0,3,6} /64.  feat index = reg*2048 + c.

#define BATCH   64
#define CDIM    2048
#define FEAT    28672           // 14 * 2048
#define TILES   16              // (b,c) tiles per block
#define NBLK    8192            // pool blocks (131072 tiles / 16)

__device__ float g_partials[NBLK];   // per-pool-block sum of squares
__device__ float g_inv[BATCH];       // 1/max(||f_b||, eps)

// 6 distinct 1-D windows (rows and cols share the set):
// 0:[0,16) 1:[0,10) 2:[4,14) 3:[0,8) 4:[3,11) 5:[6,14)
__constant__ int c_wstart[6] = {0, 0, 4, 0, 3, 6};
__constant__ int c_wlen[6]   = {16, 10, 10, 8, 8, 8};
__constant__ int   c_rw[14]  = {0, 1,1,2,2, 3,3,3,4,4,4,5,5,5};
__constant__ int   c_cw[14]  = {0, 1,2,1,2, 3,4,5,3,4,5,3,4,5};
__constant__ float c_area[14] = {1.0f/256.0f,
                                 0.01f, 0.01f, 0.01f, 0.01f,
                                 1.0f/64.0f, 1.0f/64.0f, 1.0f/64.0f,
                                 1.0f/64.0f, 1.0f/64.0f, 1.0f/64.0f,
                                 1.0f/64.0f, 1.0f/64.0f, 1.0f/64.0f};

__global__ __launch_bounds__(1024)
void rmac_pool(const float* __restrict__ x, float* __restrict__ out) {
    // cs[tile][colwin][row], row-stride 17 floats to dodge bank conflicts
    __shared__ float cs[TILES][6][17];
    __shared__ float red[32];

    const int tid  = threadIdx.x;
    const int q    = tid & 3;           // quarter-row (cols 4q..4q+3)
    const int row  = (tid >> 2) & 15;
    const int tile = tid >> 6;          // 0..15

    // Fully coalesced: warp reads 512 contiguous bytes.
    float4 v = __ldg((const float4*)(x + (size_t)blockIdx.x * 4096 + tid * 4));

    const float e0 = v.x, e1 = v.y, e2 = v.z, e3 = v.w;
    const float p01 = e0 + e1, p23 = e2 + e3, all = p01 + p23;

    // Per-lane contribution of this quarter to each column window.
    float w0 = all;                                                   // [0,16)
    float w1 = (q < 2) ? all : ((q == 2) ? p01 : 0.0f);               // [0,10)
    float w2 = (q == 1 || q == 2) ? all : ((q == 3) ? p01 : 0.0f);    // [4,14)
    float w3 = (q < 2) ? all : 0.0f;                                  // [0,8)
    float w4 = (q == 1) ? all                                         // [3,11)
             : ((q == 0) ? e3 : ((q == 2) ? (p01 + e2) : 0.0f));
    float w5 = (q == 2) ? all                                         // [6,14)
             : ((q == 1) ? p23 : ((q == 3) ? p01 : 0.0f));

    // Butterfly over the 4-lane group (q dimension): every lane gets full sums.
    const unsigned m = 0xFFFFFFFFu;
    w0 += __shfl_xor_sync(m, w0, 1);  w0 += __shfl_xor_sync(m, w0, 2);
    w1 += __shfl_xor_sync(m, w1, 1);  w1 += __shfl_xor_sync(m, w1, 2);
    w2 += __shfl_xor_sync(m, w2, 1);  w2 += __shfl_xor_sync(m, w2, 2);
    w3 += __shfl_xor_sync(m, w3, 1);  w3 += __shfl_xor_sync(m, w3, 2);
    w4 += __shfl_xor_sync(m, w4, 1);  w4 += __shfl_xor_sync(m, w4, 2);
    w5 += __shfl_xor_sync(m, w5, 1);  w5 += __shfl_xor_sync(m, w5, 2);

    // Distribute the 6 stores across the 4 lanes of the group.
    if (q == 0)      { cs[tile][0][row] = w0; cs[tile][4][row] = w4; }
    else if (q == 1) { cs[tile][1][row] = w1; cs[tile][5][row] = w5; }
    else if (q == 2) { cs[tile][2][row] = w2; }
    else             { cs[tile][3][row] = w3; }

    __syncthreads();

    // 224 threads: one (region, tile) each; tile fastest -> 64B coalesced stores
    float sq = 0.0f;
    if (tid < 224) {
        const int reg = tid >> 4;          // 0..13
        const int t   = tid & 15;
        const int rw  = c_rw[reg];
        const int cw  = c_cw[reg];
        const int st  = c_wstart[rw];
        const int len = c_wlen[rw];

        float s = 0.0f;
        #pragma unroll 4
        for (int i = 0; i < len; ++i) s += cs[t][cw][st + i];

        const float val = s * c_area[reg];
        const int gt = blockIdx.x * TILES + t;
        const int b  = gt >> 11;           // all tiles of a block share b
        const int c  = gt & 2047;
        out[(size_t)b * FEAT + reg * CDIM + c] = val;
        sq = val * val;
    }

    // Deterministic block reduction of sum-of-squares -> g_partials[block]
    #pragma unroll
    for (int o = 16; o > 0; o >>= 1) sq += __shfl_xor_sync(m, sq, o);
    const int lane = tid & 31, wid = tid >> 5;
    if (lane == 0) red[wid] = sq;
    __syncthreads();
    if (wid == 0) {
        float t2 = red[lane];
        #pragma unroll
        for (int o = 16; o > 0; o >>= 1) t2 += __shfl_xor_sync(m, t2, o);
        if (lane == 0) g_partials[blockIdx.x] = t2;
    }
}

// 64 blocks x 128 threads: reduce 128 partials per batch -> g_inv[b]
__global__ __launch_bounds__(128)
void rmac_inv() {
    __shared__ float red[4];
    const int b = blockIdx.x, tid = threadIdx.x;
    float s = g_partials[b * 128 + tid];
    #pragma unroll
    for (int o = 16; o > 0; o >>= 1) s += __shfl_xor_sync(0xFFFFFFFFu, s, o);
    if ((tid & 31) == 0) red[tid >> 5] = s;
    __syncthreads();
    if (tid == 0) {
        float t = (red[0] + red[1]) + (red[2] + red[3]);
        g_inv[b] = 1.0f / fmaxf(sqrtf(t), 1e-12f);
    }
}

// grid (14, 64), 256 threads, 2 float4 per thread: 512 float4 per block.
__global__ __launch_bounds__(256)
void rmac_scale(float* __restrict__ out) {
    const float inv = g_inv[blockIdx.y];
    float4* p = (float4*)(out + (size_t)blockIdx.y * FEAT)
              + blockIdx.x * 512 + threadIdx.x;
    float4 a = p[0];
    float4 b = p[256];
    a.x *= inv; a.y *= inv; a.z *= inv; a.w *= inv;
    b.x *= inv; b.y *= inv; b.z *= inv; b.w *= inv;
    p[0]   = a;
    p[256] = b;
}

extern "C" void kernel_launch(void* const* d_in, const int* in_sizes, int n_in,
                              void* d_out, int out_size) {
    const float* x = (const float*)d_in[0];
    float* out = (float*)d_out;

    rmac_pool<<<NBLK, 1024>>>(x, out);
    rmac_inv<<<BATCH, 128>>>();
    rmac_scale<<<dim3(14, BATCH), 256>>>(out);
}

// round 8
// speedup vs baseline: 1.7013x; 1.7013x over previous
#include <cuda_runtime.h>

// RMAC: x (64, 2048, 16, 16) f32 -> out (64, 14*2048) f32, L2-normalized rows.
// Separable regions: row-window sums per column first, then column windows.
// Row/col window set: 0:[0,16) 1:[0,10) 2:[4,14) 3:[0,8) 4:[3,11) 5:[6,14)

#define BATCH   64
#define CDIM    2048
#define FEAT    28672           // 14 * 2048
#define TILES   16              // one warp per tile, 512-thread blocks
#define NBLK    8192            // 131072 tiles / 16

__device__ float g_partials[NBLK];   // per-pool-block sum of squares

__constant__ int c_wstart[6] = {0, 0, 4, 0, 3, 6};
__constant__ int c_wlen[6]   = {16, 10, 10, 8, 8, 8};
__constant__ int   c_rw[14]  = {0, 1,1,2,2, 3,3,3,4,4,4,5,5,5};
__constant__ int   c_cw[14]  = {0, 1,2,1,2, 3,4,5,3,4,5,3,4,5};
__constant__ float c_area[14] = {1.0f/256.0f,
                                 0.01f, 0.01f, 0.01f, 0.01f,
                                 1.0f/64.0f, 1.0f/64.0f, 1.0f/64.0f,
                                 1.0f/64.0f, 1.0f/64.0f, 1.0f/64.0f,
                                 1.0f/64.0f, 1.0f/64.0f, 1.0f/64.0f};

__global__ __launch_bounds__(512)
void rmac_pool(const float* __restrict__ x, float* __restrict__ out) {
    // cs[tile][rowwin][col], col-stride 17 floats: conflict-free phase-3 reads
    __shared__ float cs[TILES][6][17];
    __shared__ float red[16];

    const int tid  = threadIdx.x;
    const int lane = tid & 31;
    const int warp = tid >> 5;          // = tile index, 0..15
    const int col  = lane & 15;
    const bool hi  = lane >= 16;        // hi half handles odd rows

    // Warp streams its 1KB tile; every LDG is one contiguous 128B line.
    const float* p = x + (size_t)blockIdx.x * 4096 + warp * 256 + lane;
    float v0 = __ldg(p +   0);   // row 2*0 + hi
    float v1 = __ldg(p +  32);   // row 2*1 + hi
    float v2 = __ldg(p +  64);
    float v3 = __ldg(p +  96);
    float v4 = __ldg(p + 128);
    float v5 = __ldg(p + 160);
    float v6 = __ldg(p + 192);
    float v7 = __ldg(p + 224);

    // Row-window partial sums for this column (this lane's 8 rows).
    const float p01 = v0 + v1, p23 = v2 + v3, p45 = v4 + v5, p67 = v6 + v7;
    float w0 = (p01 + p23) + (p45 + p67);         // rows [0,16)
    float w1 = (p01 + p23) + v4;                  // rows [0,10): i 0..4
    float w2 = (p23 + p45) + v6;                  // rows [4,14): i 2..6
    float w3 = p01 + p23;                         // rows [0,8):  i 0..3
    float w5 = (v3 + v4) + (v5 + v6);             // rows [6,14): i 3..6
    float w4 = (v2 + v3) + v4 + (hi ? v1 : v5);   // rows [3,11)

    // Combine even/odd row halves: lane l <-> l^16 hold the same column.
    const unsigned m = 0xFFFFFFFFu;
    w0 += __shfl_xor_sync(m, w0, 16);
    w1 += __shfl_xor_sync(m, w1, 16);
    w2 += __shfl_xor_sync(m, w2, 16);
    w3 += __shfl_xor_sync(m, w3, 16);
    w4 += __shfl_xor_sync(m, w4, 16);
    w5 += __shfl_xor_sync(m, w5, 16);

    if (!hi) {
        cs[warp][0][col] = w0;
        cs[warp][1][col] = w1;
        cs[warp][2][col] = w2;
        cs[warp][3][col] = w3;
        cs[warp][4][col] = w4;
        cs[warp][5][col] = w5;
    }

    __syncthreads();

    // Phase 3: 224 threads, one (region, tile) each; t fastest -> 64B stores.
    float sq = 0.0f;
    if (tid < 224) {
        const int reg = tid >> 4;          // 0..13
        const int t   = tid & 15;
        const int rw  = c_rw[reg];
        const int cw  = c_cw[reg];
        const int st  = c_wstart[cw];
        const int len = c_wlen[cw];

        float s = 0.0f;
        #pragma unroll 4
        for (int i = 0; i < len; ++i) s += cs[t][rw][st + i];

        const float val = s * c_area[reg];
        const int gt = blockIdx.x * TILES + t;
        const int b  = gt >> 11;
        const int c  = gt & 2047;
        out[(size_t)b * FEAT + reg * CDIM + c] = val;
        sq = val * val;
    }

    // Deterministic block reduction of sum of squares.
    #pragma unroll
    for (int o = 16; o > 0; o >>= 1) sq += __shfl_xor_sync(m, sq, o);
    if (lane == 0) red[warp] = sq;
    __syncthreads();
    if (warp == 0) {
        float t2 = (lane < 16) ? red[lane] : 0.0f;
        #pragma unroll
        for (int o = 8; o > 0; o >>= 1) t2 += __shfl_xor_sync(m, t2, o);
        if (lane == 0) g_partials[blockIdx.x] = t2;
    }
}

// grid (14, 64), 256 threads. Each block re-reduces its batch's 128 partials
// (deterministic fixed tree), then scales its 2048-float slice in place.
__global__ __launch_bounds__(256)
void rmac_scale(float* __restrict__ out) {
    __shared__ float red[4];
    __shared__ float s_inv;
    const int b = blockIdx.y, tid = threadIdx.x;
    const unsigned m = 0xFFFFFFFFu;

    if (tid < 128) {
        float s = g_partials[b * 128 + tid];
        #pragma unroll
        for (int o = 16; o > 0; o >>= 1) s += __shfl_xor_sync(m, s, o);
        if ((tid & 31) == 0) red[tid >> 5] = s;
    }
    __syncthreads();
    if (tid == 0) {
        float t = (red[0] + red[1]) + (red[2] + red[3]);
        s_inv = 1.0f / fmaxf(sqrtf(t), 1e-12f);
    }
    __syncthreads();
    const float inv = s_inv;

    float4* p = (float4*)(out + (size_t)b * FEAT) + blockIdx.x * 512 + tid;
    float4 a = p[0];
    float4 c = p[256];
    a.x *= inv; a.y *= inv; a.z *= inv; a.w *= inv;
    c.x *= inv; c.y *= inv; c.z *= inv; c.w *= inv;
    p[0]   = a;
    p[256] = c;
}

extern "C" void kernel_launch(void* const* d_in, const int* in_sizes, int n_in,
                              void* d_out, int out_size) {
    const float* x = (const float*)d_in[0];
    float* out = (float*)d_out;

    rmac_pool<<<NBLK, 512>>>(x, out);
    rmac_scale<<<dim3(14, BATCH), 256>>>(out);
}